// round 17
// baseline (speedup 1.0000x reference)
#include <cuda_runtime.h>
#include <cuda_bf16.h>

#define D 128
#define MAXN 50176    // padded N
#define MAXE 524288
#define LMAX 3

// ---------------- scratch (device globals, no allocation) ----------------
__device__ float g_x[MAXN * D];     // embedding (layer-0 residual input)
__device__ float g_h[MAXN * D];     // activations ping
__device__ float g_h2[MAXN * D];    // activations pong
__device__ float g_inorm[MAXN];
__device__ float g_colsum[D];
__device__ float g_colsq[D];
__device__ float g_scale[D];        // BN scale of PREVIOUS layer (init 1)
__device__ float g_shift[D];        // BN shift of PREVIOUS layer (init 0)
__device__ unsigned g_blkdone;      // last-block counter for fused stats

// CSR structures
__device__ int   g_outdeg[MAXN];
__device__ int   g_indeg[MAXN];
__device__ int   g_rowptr[MAXN + 1];
__device__ int   g_cursor[MAXN];
__device__ int   g_chunksum[256];
__device__ int   g_chunkoff[256];
__device__ int2  g_epack[MAXE];     // (src, onorm-bits)
__device__ int2  g_epack0[MAXE];    // (node_id[src], onorm-bits) for layer 0

// weights pre-split to bf16 hi/lo, pre-permuted into mma B-fragment order
__device__ __align__(16) unsigned short g_bfrag[LMAX][4][16384];

// ---------------- mma / split helpers ----------------
__device__ __forceinline__ void mma16816(float* c, const uint4& a, const uint2& b) {
    asm volatile(
        "mma.sync.aligned.m16n8k16.row.col.f32.bf16.bf16.f32 "
        "{%0,%1,%2,%3}, {%4,%5,%6,%7}, {%8,%9}, {%0,%1,%2,%3};"
        : "+f"(c[0]), "+f"(c[1]), "+f"(c[2]), "+f"(c[3])
        : "r"(a.x), "r"(a.y), "r"(a.z), "r"(a.w), "r"(b.x), "r"(b.y));
}
__device__ __forceinline__ void split2(float x, float y,
                                       unsigned& hi, unsigned& lo) {
    __nv_bfloat162 h2 = __floats2bfloat162_rn(x, y);
    hi = *(unsigned*)&h2;
    float rx = x - __bfloat162float(h2.x);
    float ry = y - __bfloat162float(h2.y);
    __nv_bfloat162 l2 = __floats2bfloat162_rn(rx, ry);
    lo = *(unsigned*)&l2;
}

// ---------------- init: zero deg, identity BN, weight frags, emb gather --
__global__ void init_kernel(const int* __restrict__ node_ids,
                            const float* __restrict__ emb,
                            const float* __restrict__ Ws,
                            const float* __restrict__ Rws, int L, int N) {
    int id = blockIdx.x * blockDim.x + threadIdx.x;
    if (id == 0) g_blkdone = 0u;
    if (id < N) { g_outdeg[id] = 0; g_indeg[id] = 0; }
    if (id < D) {
        g_scale[id] = 1.0f; g_shift[id] = 0.0f;
        g_colsum[id] = 0.0f; g_colsq[id] = 0.0f;
    }
    if (id < N * 32) {
        int i = id >> 5;
        int c = id & 31;
        ((float4*)g_x)[id] = ((const float4*)emb)[node_ids[i] * 32 + c];
    }
    if (id < L * 32768) {
        int l = id >> 15;
        int rest = id & 32767;
        int which = rest >> 14;          // 0 = W, 1 = R
        int e = rest & 16383;
        int k = e >> 7, n = e & 127;
        float w = (which ? Rws : Ws)[l * 16384 + k * 128 + n];
        __nv_bfloat16 hb = __float2bfloat16(w);
        __nv_bfloat16 lb = __float2bfloat16(w - __bfloat162float(hb));
        int kt = k >> 4, kk = k & 15, nt = n >> 3, g = n & 7;
        int t = (kk >> 1) & 3, reg = kk >> 3, half = kk & 1;
        int lane = g * 4 + t;
        int slot = ((((kt * 16 + nt) * 32 + lane) * 2 + reg) << 1) + half;
        g_bfrag[l][which * 2 + 0][slot] = *(unsigned short*)&hb;
        g_bfrag[l][which * 2 + 1][slot] = *(unsigned short*)&lb;
    }
}

__global__ void deg_kernel(const int* __restrict__ src,
                           const int* __restrict__ dst, int E) {
    int e = blockIdx.x * blockDim.x + threadIdx.x;
    if (e < E) {
        atomicAdd(&g_outdeg[src[e]], 1);
        atomicAdd(&g_indeg[dst[e]], 1);
    }
}

// ---------------- scan of indeg -> rowptr; inorm finalize in scan1 -------
__global__ void scan1_kernel(int N) {
    __shared__ int sd[256];
    int i = blockIdx.x * 256 + threadIdx.x;
    int dv = (i < N) ? g_indeg[i] : 0;
    sd[threadIdx.x] = dv;
    if (i < N) g_inorm[i] = (dv > 0) ? rsqrtf((float)dv) : 0.f;
    __syncthreads();
    for (int s = 128; s > 0; s >>= 1) {
        if (threadIdx.x < s) sd[threadIdx.x] += sd[threadIdx.x + s];
        __syncthreads();
    }
    if (threadIdx.x == 0) g_chunksum[blockIdx.x] = sd[0];
}

__global__ void scan2_kernel(int nch) {
    __shared__ int sd[256];
    int t = threadIdx.x;
    int v = (t < nch) ? g_chunksum[t] : 0;
    sd[t] = v;
    __syncthreads();
    for (int off = 1; off < 256; off <<= 1) {
        int val = (t >= off) ? sd[t - off] : 0;
        __syncthreads();
        sd[t] += val;
        __syncthreads();
    }
    if (t < nch) g_chunkoff[t] = sd[t] - v;  // exclusive
}

__global__ void scan3_kernel(int N, int E) {
    __shared__ int sd[256];
    int t = threadIdx.x;
    int i = blockIdx.x * 256 + t;
    int v = (i < N) ? g_indeg[i] : 0;
    sd[t] = v;
    __syncthreads();
    for (int off = 1; off < 256; off <<= 1) {
        int val = (t >= off) ? sd[t - off] : 0;
        __syncthreads();
        sd[t] += val;
        __syncthreads();
    }
    if (i < N) {
        int rp = g_chunkoff[blockIdx.x] + sd[t] - v;
        g_rowptr[i] = rp;
        g_cursor[i] = rp;
    }
    if (i == 0) g_rowptr[N] = E;
}

// fill: onorm inline; also writes layer-0 pack (node_id[src], w)
__global__ void fill_kernel(const int* __restrict__ src,
                            const int* __restrict__ dst,
                            const int* __restrict__ node_ids, int E) {
    int e = blockIdx.x * blockDim.x + threadIdx.x;
    if (e < E) {
        int s = src[e];
        int d = dst[e];
        float wt = rsqrtf((float)g_outdeg[s]);
        int p = atomicAdd(&g_cursor[d], 1);
        int wb = __float_as_int(wt);
        g_epack[p] = make_int2(s, wb);
        g_epack0[p] = make_int2(node_ids[s], wb);
    }
}

// ---------------- persistent fused gather + dual tc GEMM (bf16x3) --------
// Ping-pong: layer l reads hin (read-only this launch), writes hout.
// h = relu(gathered @ W + b) + relu(BN(hin) @ Rw + rb); reg BN stats;
// last finishing block computes next layer's scale/shift.
#define SM_BWH  0
#define SM_BWL  32768
#define SM_BRH  65536
#define SM_BRL  98304
#define SM_A1H  131072
#define SM_A1L  147456
#define SM_A2H  163840
#define SM_A2L  180224
#define SM_BIAS 196608
#define SM_RB   197120
#define SM_SC   197632
#define SM_SH   198144
#define SM_CS   198656
#define SM_CQ   200704
#define TC_SMEM 202752
// Hs (64x64 float2, xor-swizzled) overlays SM_A1H..SM_A1H+32768

__global__ __launch_bounds__(256, 1)
void gemm_tc_kernel(const float* __restrict__ emb,
                    const float* __restrict__ b, const float* __restrict__ rb,
                    const float* __restrict__ gamma,
                    const float* __restrict__ beta,
                    int l, int N) {
    extern __shared__ char smc[];
    const int tid = threadIdx.x;
    const int lane = tid & 31;
    const int wid = tid >> 5;
    const bool br1 = (wid >= 4);
    const int wl = wid & 3;
    const int mtbase = (wl & 1) * 2;
    const int nh = wl >> 1;
    const int use_h = (l > 0);
    // ping-pong: layer l output buffer = (l&1) ? g_h2 : g_h
    const float* hprev = ((l - 1) & 1) ? g_h2 : g_h;   // valid for l>=1
    float* hout = (l & 1) ? g_h2 : g_h;
    const float* buf  = use_h ? hprev : g_x;    // residual input (RO)
    const float* gbuf = use_h ? hprev : emb;    // gather source  (RO)
    const int2*  ep   = use_h ? g_epack : g_epack0;

    unsigned* A1H = (unsigned*)(smc + SM_A1H);
    unsigned* A1L = (unsigned*)(smc + SM_A1L);
    unsigned* A2H = (unsigned*)(smc + SM_A2H);
    unsigned* A2L = (unsigned*)(smc + SM_A2L);
    float* bsm  = (float*)(smc + SM_BIAS);
    float* rbsm = (float*)(smc + SM_RB);
    float* scsm = (float*)(smc + SM_SC);
    float* shsm = (float*)(smc + SM_SH);
    float* scs4 = (float*)(smc + SM_CS);
    float* scq4 = (float*)(smc + SM_CQ);
    float2* Hp = (float2*)(smc + SM_A1H);

    // one-time: copy pre-permuted weight fragments (128 KB) + vectors
    {
        const uint4* src4 = (const uint4*)g_bfrag[l];
        uint4* dst4 = (uint4*)smc;
        for (int i = tid; i < 8192; i += 256) dst4[i] = src4[i];
        if (tid < 128) {
            bsm[tid] = b[tid];
            rbsm[tid] = rb[tid];
            scsm[tid] = g_scale[tid];
            shsm[tid] = g_shift[tid];
            scs4[tid] = 0.f; scs4[128 + tid] = 0.f;
            scs4[256 + tid] = 0.f; scs4[384 + tid] = 0.f;
            scq4[tid] = 0.f; scq4[128 + tid] = 0.f;
            scq4[256 + tid] = 0.f; scq4[384 + tid] = 0.f;
        }
    }
    __syncthreads();  // scsm/shsm ready before first gather

    const unsigned* Ah = br1 ? A2H : A1H;
    const unsigned* Al = br1 ? A2L : A1L;
    const unsigned* Bh = (const unsigned*)(smc + (br1 ? SM_BRH : SM_BWH));
    const unsigned* Bl = (const unsigned*)(smc + (br1 ? SM_BRL : SM_BWL));

    float cs[16], cq[16];
#pragma unroll
    for (int i = 0; i < 16; i++) { cs[i] = 0.f; cq[i] = 0.f; }

    const int nchunks = (N + 63) / 64;
    // pa = gathered+folded agg rows, px = raw residual rows.
    float4 pa[8], px[8];

    // ---- inline gather for a chunk base; results into pa/px ----
#define GATHER_CHUNK(base_)                                                 \
    do {                                                                    \
        int base = (base_);                                                 \
        _Pragma("unroll")                                                   \
        for (int it = 0; it < 8; ++it) {                                    \
            int idx = tid + it * 256;                                       \
            int row = base + (idx >> 5);                                    \
            int q = idx & 31;                                               \
            float4 z = make_float4(0.f, 0.f, 0.f, 0.f);                     \
            pa[it] = z; px[it] = z;                                         \
            if (row < N) {                                                  \
                px[it] = ((const float4*)buf)[row * 32 + q];                \
                int beg = g_rowptr[row];                                    \
                int end = g_rowptr[row + 1];                                \
                float4 acc = z;                                             \
                float sw = 0.f;                                             \
                _Pragma("unroll 4")                                         \
                for (int j = beg; j < end; ++j) {                           \
                    int2 e = ep[j];                                         \
                    float wt = __int_as_float(e.y);                         \
                    sw += wt;                                               \
                    float4 v = ((const float4*)gbuf)[e.x * 32 + q];         \
                    acc.x += wt * v.x;                                      \
                    acc.y += wt * v.y;                                      \
                    acc.z += wt * v.z;                                      \
                    acc.w += wt * v.w;                                      \
                }                                                           \
                float inn = g_inorm[row];                                   \
                float4 sc = ((const float4*)scsm)[q];                       \
                float4 sh = ((const float4*)shsm)[q];                       \
                pa[it].x = inn * (sc.x * acc.x + sh.x * sw);                \
                pa[it].y = inn * (sc.y * acc.y + sh.y * sw);                \
                pa[it].z = inn * (sc.z * acc.z + sh.z * sw);                \
                pa[it].w = inn * (sc.w * acc.w + sh.w * sw);                \
            }                                                               \
        }                                                                   \
    } while (0)

    GATHER_CHUNK(blockIdx.x * 64);  // prologue: first chunk

    for (int chunk = blockIdx.x; chunk < nchunks; chunk += gridDim.x) {
        const int rowbase = chunk * 64;
        __syncthreads();  // previous chunk fully consumed (Hs/A frags)

        // ---- stage gathered rows into fragments (A1=agg, A2=BN(buf)) ----
#pragma unroll
        for (int it = 0; it < 8; ++it) {
            int idx = tid + it * 256;
            int r = idx >> 5, q = idx & 31;
            float4 va = pa[it];
            float4 vb = px[it];
            float4 sc = ((const float4*)scsm)[q];
            float4 sh = ((const float4*)shsm)[q];
            float4 vx;
            vx.x = vb.x * sc.x + sh.x;
            vx.y = vb.y * sc.y + sh.y;
            vx.z = vb.z * sc.z + sh.z;
            vx.w = vb.w * sc.w + sh.w;
            unsigned h1a, l1a, h1b, l1b, h2a, l2a, h2b, l2b;
            split2(va.x, va.y, h1a, l1a);
            split2(va.z, va.w, h1b, l1b);
            split2(vx.x, vx.y, h2a, l2a);
            split2(vx.z, vx.w, h2b, l2b);
            int p0 = 2 * q, p1 = 2 * q + 1;
            int mt = r >> 4, rr = r & 15;
            int kt = p0 >> 3;
            int pp0 = p0 & 7, pp1 = p1 & 7;
            int ln0 = (rr & 7) * 4 + (pp0 & 3);
            int ln1 = (rr & 7) * 4 + (pp1 & 3);
            int rg0 = (rr >> 3) + 2 * (pp0 >> 2);
            int rg1 = (rr >> 3) + 2 * (pp1 >> 2);
            int u0 = ((mt * 8 + kt) * 32 + ln0) * 4 + rg0;
            int u1 = ((mt * 8 + kt) * 32 + ln1) * 4 + rg1;
            A1H[u0] = h1a; A1L[u0] = l1a;
            A1H[u1] = h1b; A1L[u1] = l1b;
            A2H[u0] = h2a; A2L[u0] = l2a;
            A2H[u1] = h2b; A2L[u1] = l2b;
        }
        __syncthreads();

        // ---- inline gather for next chunk (overlaps mma below) ----
        int nextbase = rowbase + gridDim.x * 64;
        if (nextbase < N) GATHER_CHUNK(nextbase);

        // ---- mma mainloop ----
        float c[2][8][4];
#pragma unroll
        for (int i = 0; i < 2; i++)
#pragma unroll
            for (int j = 0; j < 8; j++)
#pragma unroll
                for (int q = 0; q < 4; q++) c[i][j][q] = 0.f;

#pragma unroll
        for (int kt = 0; kt < 8; ++kt) {
            uint4 ah0 = *(const uint4*)&Ah[(((mtbase + 0) * 8 + kt) * 32 + lane) * 4];
            uint4 ah1 = *(const uint4*)&Ah[(((mtbase + 1) * 8 + kt) * 32 + lane) * 4];
            uint4 al0 = *(const uint4*)&Al[(((mtbase + 0) * 8 + kt) * 32 + lane) * 4];
            uint4 al1 = *(const uint4*)&Al[(((mtbase + 1) * 8 + kt) * 32 + lane) * 4];
#pragma unroll
            for (int j = 0; j < 8; ++j) {
                int nt = nh * 8 + j;
                uint2 bh = *(const uint2*)&Bh[((kt * 16 + nt) * 32 + lane) * 2];
                uint2 bl = *(const uint2*)&Bl[((kt * 16 + nt) * 32 + lane) * 2];
                mma16816(c[0][j], ah0, bh);
                mma16816(c[0][j], ah0, bl);
                mma16816(c[0][j], al0, bh);
                mma16816(c[1][j], ah1, bh);
                mma16816(c[1][j], ah1, bl);
                mma16816(c[1][j], al1, bh);
            }
        }
        __syncthreads();  // all mma done before Hs overlays A1 frags

        // ---- branch 0: Hs = relu(agg@W + b)  (xor-swizzled smem) ----
        if (!br1) {
#pragma unroll
            for (int mt2 = 0; mt2 < 2; ++mt2)
#pragma unroll
                for (int j = 0; j < 8; ++j) {
                    int nt = nh * 8 + j;
                    int r0 = (mtbase + mt2) * 16 + (lane >> 2);
                    int cp = nt * 4 + (lane & 3);
                    float b0v = bsm[cp * 2], b1v = bsm[cp * 2 + 1];
                    float* cc = c[mt2][j];
                    Hp[r0 * 64 + (cp ^ (r0 & 7))] =
                        make_float2(fmaxf(cc[0] + b0v, 0.f),
                                    fmaxf(cc[1] + b1v, 0.f));
                    int r1 = r0 + 8;
                    Hp[r1 * 64 + (cp ^ (r1 & 7))] =
                        make_float2(fmaxf(cc[2] + b0v, 0.f),
                                    fmaxf(cc[3] + b1v, 0.f));
                }
        }
        __syncthreads();

        // ---- branch 1: h = relu(x@Rw + rb) + Hs; write + stats ----
        if (br1) {
#pragma unroll
            for (int mt2 = 0; mt2 < 2; ++mt2)
#pragma unroll
                for (int j = 0; j < 8; ++j) {
                    int nt = nh * 8 + j;
                    int r0 = (mtbase + mt2) * 16 + (lane >> 2);
                    int cp = nt * 4 + (lane & 3);
                    float rb0 = rbsm[cp * 2], rb1 = rbsm[cp * 2 + 1];
                    float* cc = c[mt2][j];
                    int row0 = rowbase + r0;
                    if (row0 < N) {
                        float2 hs = Hp[r0 * 64 + (cp ^ (r0 & 7))];
                        float v0 = fmaxf(cc[0] + rb0, 0.f) + hs.x;
                        float v1 = fmaxf(cc[1] + rb1, 0.f) + hs.y;
                        ((float2*)hout)[row0 * 64 + cp] = make_float2(v0, v1);
                        cs[j * 2] += v0;     cq[j * 2] += v0 * v0;
                        cs[j * 2 + 1] += v1; cq[j * 2 + 1] += v1 * v1;
                    }
                    int r1 = r0 + 8;
                    int row1 = rowbase + r1;
                    if (row1 < N) {
                        float2 hs = Hp[r1 * 64 + (cp ^ (r1 & 7))];
                        float v0 = fmaxf(cc[2] + rb0, 0.f) + hs.x;
                        float v1 = fmaxf(cc[3] + rb1, 0.f) + hs.y;
                        ((float2*)hout)[row1 * 64 + cp] = make_float2(v0, v1);
                        cs[j * 2] += v0;     cq[j * 2] += v0 * v0;
                        cs[j * 2 + 1] += v1; cq[j * 2 + 1] += v1 * v1;
                    }
                }
        }
    }

    // ---- flush BN stats ----
    __syncthreads();
    if (br1) {
#pragma unroll
        for (int i = 0; i < 16; i++) {
#pragma unroll
            for (int off = 4; off <= 16; off <<= 1) {
                cs[i] += __shfl_xor_sync(0xffffffffu, cs[i], off);
                cq[i] += __shfl_xor_sync(0xffffffffu, cq[i], off);
            }
        }
        if (lane < 4) {
#pragma unroll
            for (int j = 0; j < 8; j++) {
#pragma unroll
                for (int h2 = 0; h2 < 2; h2++) {
                    int col = nh * 64 + j * 8 + lane * 2 + h2;
                    atomicAdd(&scs4[wl * 128 + col], cs[j * 2 + h2]);
                    atomicAdd(&scq4[wl * 128 + col], cq[j * 2 + h2]);
                }
            }
        }
    }
    __syncthreads();
    if (tid < 128) {
        float s = scs4[tid] + scs4[128 + tid] + scs4[256 + tid] + scs4[384 + tid];
        float q = scq4[tid] + scq4[128 + tid] + scq4[256 + tid] + scq4[384 + tid];
        atomicAdd(&g_colsum[tid], s);
        atomicAdd(&g_colsq[tid], q);
    }

    // ---- fused stats: last finishing block computes scale/shift ----
    __threadfence();
    __shared__ unsigned s_last;
    if (tid == 0) s_last = (atomicAdd(&g_blkdone, 1u) == gridDim.x - 1u);
    __syncthreads();
    if (s_last) {
        if (tid < 128) {
            float invN = 1.0f / (float)N;
            float mu = g_colsum[tid] * invN;
            float var = g_colsq[tid] * invN - mu * mu;
            var = fmaxf(var, 0.f);
            float istd = rsqrtf(var + 1e-5f);
            float sc = gamma[tid] * istd;
            g_scale[tid] = sc;
            g_shift[tid] = beta[tid] - mu * sc;
            g_colsum[tid] = 0.f;
            g_colsq[tid] = 0.f;
        }
        if (tid == 0) g_blkdone = 0u;
    }
}

// ---------------- final normalize (last layer only) ----------------
__global__ void normalize_kernel(int N, int final_pong, float* __restrict__ out) {
    const float* hfin = final_pong ? g_h2 : g_h;
    int total = N * 32;
    for (int idx = blockIdx.x * blockDim.x + threadIdx.x; idx < total;
         idx += gridDim.x * blockDim.x) {
        int c4 = idx & 31;
        float4 v = ((const float4*)hfin)[idx];
        float4 s = ((const float4*)g_scale)[c4];
        float4 sh = ((const float4*)g_shift)[c4];
        float4 r;
        r.x = v.x * s.x + sh.x;
        r.y = v.y * s.y + sh.y;
        r.z = v.z * s.z + sh.z;
        r.w = v.w * s.w + sh.w;
        ((float4*)out)[idx] = r;
    }
}

// ---------------- launch ----------------
extern "C" void kernel_launch(void* const* d_in, const int* in_sizes, int n_in,
                              void* d_out, int out_size) {
    const int*   node_ids = (const int*)d_in[0];
    const int*   src      = (const int*)d_in[1];
    const int*   dst      = (const int*)d_in[2];
    const float* emb      = (const float*)d_in[3];
    const float* Ws       = (const float*)d_in[4];
    const float* bs       = (const float*)d_in[5];
    const float* Rws      = (const float*)d_in[6];
    const float* Rbs      = (const float*)d_in[7];
    const float* gammas   = (const float*)d_in[8];
    const float* betas    = (const float*)d_in[9];

    const int N = in_sizes[0];
    const int E = in_sizes[1];
    const int L = in_sizes[4] / (D * D);
    const int nch = (N + 255) / 256;

    cudaFuncSetAttribute(gemm_tc_kernel,
                         cudaFuncAttributeMaxDynamicSharedMemorySize, TC_SMEM);

    // prep: init (zero deg + BN + wfrags + emb gather), deg, scans, fill
    int ithreads = N * 32;
    if (L * 32768 > ithreads) ithreads = L * 32768;
    init_kernel<<<(ithreads + 255) / 256, 256>>>(node_ids, emb, Ws, Rws, L, N);
    deg_kernel<<<(E + 255) / 256, 256>>>(src, dst, E);
    scan1_kernel<<<nch, 256>>>(N);
    scan2_kernel<<<1, 256>>>(nch);
    scan3_kernel<<<nch, 256>>>(N, E);
    fill_kernel<<<(E + 255) / 256, 256>>>(src, dst, node_ids, E);

    // layers: fused gather + persistent tc GEMM (+fused stats), ping-pong
    for (int l = 0; l < L; ++l) {
        gemm_tc_kernel<<<148, 256, TC_SMEM>>>(
            emb, bs + l * D, Rbs + l * D, gammas + l * D, betas + l * D,
            l, N);
    }
    normalize_kernel<<<512, 256>>>(N, (L - 1) & 1, (float*)d_out);
}